// round 13
// baseline (speedup 1.0000x reference)
#include <cuda_runtime.h>

// out[n, f, h] = x[n, f] * W[f, h] + b[f, h]
// BATCH=16384, F=128, H=64, fp32. 512 MiB output -> HBM write-stream bound.
//
// R12: R2 skeleton (best so far, 76.0us), single variable: N_PER_THREAD 16->8.
// N-sweep so far: N=1 -> 115us, N=16 -> 76.0, N=32 -> 79.5. Testing N=8:
// 2x more blocks (16384) = finer store-stream interleaving per wave, while
// W/b register amortization (8x) still holds.

#define BATCH 16384
#define NFEAT 128
#define HID   64
#define H4    (HID / 4)               // 16
#define FH    (NFEAT * H4)            // 2048 (f,h4) pairs
#define TPB   256
#define FH_BLOCKS (FH / TPB)          // 8
#define N_PER_THREAD 8
#define N_CHUNKS (BATCH / N_PER_THREAD) // 2048

__global__ __launch_bounds__(TPB)
void ifll_kernel(const float* __restrict__ x,
                 const float4* __restrict__ W4,
                 const float4* __restrict__ b4,
                 float4* __restrict__ out)
{
    // blockIdx.x = n_chunk * FH_BLOCKS + f_block
    int fh = (blockIdx.x & (FH_BLOCKS - 1)) * TPB + threadIdx.x; // 0..2047
    int n0 = (blockIdx.x >> 3) * N_PER_THREAD;

    int f = fh >> 4;                  // feature index

    // Per-thread invariant weights: loaded once, amortized over 8 rows.
    float4 w  = __ldg(&W4[fh]);
    float4 bb = __ldg(&b4[fh]);

    const float* xp = x + (size_t)n0 * NFEAT + f;
    float4*      op = out + (size_t)n0 * FH + fh;

    #pragma unroll
    for (int i = 0; i < N_PER_THREAD; i++) {
        float xv = __ldg(xp + i * NFEAT);
        float4 o;
        o.x = fmaf(xv, w.x, bb.x);
        o.y = fmaf(xv, w.y, bb.y);
        o.z = fmaf(xv, w.z, bb.z);
        o.w = fmaf(xv, w.w, bb.w);
        __stcs(op + (size_t)i * FH, o);   // streaming store, evict-first
    }
}

extern "C" void kernel_launch(void* const* d_in, const int* in_sizes, int n_in,
                              void* d_out, int out_size)
{
    const float*  x  = (const float*)d_in[0];
    const float4* W4 = (const float4*)d_in[1];
    const float4* b4 = (const float4*)d_in[2];
    float4* out = (float4*)d_out;

    const int blocks = N_CHUNKS * FH_BLOCKS;  // 16384
    ifll_kernel<<<blocks, TPB>>>(x, W4, b4, out);
}

// round 14
// speedup vs baseline: 1.3990x; 1.3990x over previous
#include <cuda_runtime.h>

// out[n, f, h] = x[n, f] * W[f, h] + b[f, h]
// BATCH=16384, F=128, H=64, fp32. 512 MiB output -> HBM write-stream bound.
//
// FINAL (= R2, measured best 76.0us, ~6.1 TB/s effective write BW):
// - thread owns one (f,h4) pair x 16 batch rows
// - W/b float4 register-resident, amortized 16x
// - 1 broadcast LDG.32 (x) + 4 FMA + 1 STG.128 __stcs per 16 output floats
// - warp stores 512 B fully-contiguous segments; evict-first keeps L2 clean
// Converged axes: store width (128b > 256b), policy (.cs > writeback),
// N/thread (16 optimal of {1,8,16,32}), x path (LDG ~= smem-staged).

#define BATCH 16384
#define NFEAT 128
#define HID   64
#define H4    (HID / 4)               // 16
#define FH    (NFEAT * H4)            // 2048 (f,h4) pairs
#define TPB   256
#define FH_BLOCKS (FH / TPB)          // 8
#define N_PER_THREAD 16
#define N_CHUNKS (BATCH / N_PER_THREAD) // 1024

__global__ __launch_bounds__(TPB)
void ifll_kernel(const float* __restrict__ x,
                 const float4* __restrict__ W4,
                 const float4* __restrict__ b4,
                 float4* __restrict__ out)
{
    // blockIdx.x = n_chunk * FH_BLOCKS + f_block
    int fh = (blockIdx.x & (FH_BLOCKS - 1)) * TPB + threadIdx.x; // 0..2047
    int n0 = (blockIdx.x >> 3) * N_PER_THREAD;

    int f = fh >> 4;                  // feature index

    // Per-thread invariant weights: loaded once, amortized over 16 rows.
    float4 w  = __ldg(&W4[fh]);       // W4[f*H4 + h4] == W4[fh]
    float4 bb = __ldg(&b4[fh]);

    const float* xp = x + (size_t)n0 * NFEAT + f;
    float4*      op = out + (size_t)n0 * FH + fh;

    #pragma unroll
    for (int i = 0; i < N_PER_THREAD; i++) {
        float xv = __ldg(xp + i * NFEAT);
        float4 o;
        o.x = fmaf(xv, w.x, bb.x);
        o.y = fmaf(xv, w.y, bb.y);
        o.z = fmaf(xv, w.z, bb.z);
        o.w = fmaf(xv, w.w, bb.w);
        __stcs(op + (size_t)i * FH, o);   // streaming store, evict-first
    }
}

extern "C" void kernel_launch(void* const* d_in, const int* in_sizes, int n_in,
                              void* d_out, int out_size)
{
    const float*  x  = (const float*)d_in[0];
    const float4* W4 = (const float4*)d_in[1];
    const float4* b4 = (const float4*)d_in[2];
    float4* out = (float4*)d_out;

    const int blocks = N_CHUNKS * FH_BLOCKS;  // 8192
    ifll_kernel<<<blocks, TPB>>>(x, W4, b4, out);
}